// round 6
// baseline (speedup 1.0000x reference)
#include <cuda_runtime.h>
#include <cuda_fp16.h>
#include <cstdint>

#define HDIM 4096
#define NEXP 64
#define BM   128
#define BK   64
#define TPAD 72      // padded halves per smem row (144B): conflict-free STS.128 + ldmatrix
#define NTHR 512
#define NCHUNK (HDIM / BK)

// dynamic smem (bytes), double buffered
#define XH_OFF 0
#define XL_OFF (BM * TPAD * 2)                  // 18432
#define WH_OFF (2 * BM * TPAD * 2)              // 36864
#define WL_OFF (WH_OFF + NEXP * TPAD * 2)       // 46080
#define BUF_BYTES (WL_OFF + NEXP * TPAD * 2)    // 55296
#define SMEM_TOTAL (2 * BUF_BYTES)              // 110592

__device__ float    g_z[128];
__device__ unsigned g_cnt = 0;

__device__ __forceinline__ void split2(float f0, float f1, unsigned& hi, unsigned& lo) {
    __half2 h = __floats2half2_rn(f0, f1);
    float2 hf = __half22float2(h);
    __half2 l = __floats2half2_rn(f0 - hf.x, f1 - hf.y);
    hi = *reinterpret_cast<unsigned*>(&h);
    lo = *reinterpret_cast<unsigned*>(&l);
}
__device__ __forceinline__ void ldsm4(unsigned* d, uint32_t addr) {
    asm volatile("ldmatrix.sync.aligned.m8n8.x4.shared.b16 {%0,%1,%2,%3}, [%4];"
                 : "=r"(d[0]), "=r"(d[1]), "=r"(d[2]), "=r"(d[3]) : "r"(addr));
}
__device__ __forceinline__ void mma16816(float* c, const unsigned* a, unsigned b0, unsigned b1) {
    asm volatile("mma.sync.aligned.m16n8k16.row.col.f32.f16.f16.f32 "
                 "{%0,%1,%2,%3}, {%4,%5,%6,%7}, {%8,%9}, {%0,%1,%2,%3};"
                 : "+f"(c[0]), "+f"(c[1]), "+f"(c[2]), "+f"(c[3])
                 : "r"(a[0]), "r"(a[1]), "r"(a[2]), "r"(a[3]), "r"(b0), "r"(b1));
}

__global__ __launch_bounds__(NTHR, 1) void router_ws(
    const float* __restrict__ X, const float* __restrict__ W,
    float* __restrict__ out, int T)
{
    extern __shared__ char smem[];
    __shared__ float zred[BM];
    const uint32_t sb = (uint32_t)__cvta_generic_to_shared(smem);

    const int tid  = threadIdx.x;
    const int lane = tid & 31;
    const int wid  = tid >> 5;          // 0-7 producers, 8-15 consumers
    const int tok0 = blockIdx.x * BM;

    // ======================= PRODUCER state (wid < 8, tid < 256) =======================
    const int ptid = tid;                           // 0..255 for producers
    const int xr = ptid >> 1, xc = (ptid & 1) * 32; // X: 2 thr/row, 32 floats
    const int wr = ptid >> 2, wc = (ptid & 3) * 16; // W: 4 thr/row, 16 floats
    const float* xg = X + (size_t)(tok0 + xr) * HDIM + xc;
    const float* wg = W + (size_t)wr * HDIM + wc;
    float4 xv[8], wv[4];

    // ======================= CONSUMER state (wid >= 8) =======================
    const int w2 = wid - 8;             // 0..7
    const int m0 = (w2 & 3) * 32;       // token rows m0..m0+31
    const int n0 = (w2 >> 2) * 32;      // expert cols n0..n0+31
    const int g  = lane >> 3, r = lane & 7;
    // A m16-tile offsets (two per warp)
    uint32_t aOff[2];
    #pragma unroll
    for (int mt = 0; mt < 2; ++mt)
        aOff[mt] = (uint32_t)(((m0 + mt * 16 + r + ((g & 1) << 3)) * TPAD + ((g >> 1) << 3)) * 2);
    const int bRow = r + ((g >> 1) << 3);
    const int bK   = (g & 1) << 3;

    float acc[2][4][4];                 // [m16 tile][n8 group][frag]
    #pragma unroll
    for (int mt = 0; mt < 2; ++mt)
        #pragma unroll
        for (int j = 0; j < 4; ++j)
            #pragma unroll
            for (int q = 0; q < 4; ++q) acc[mt][j][q] = 0.f;

    // ---- prologue: producers load+convert chunk 0, prefetch chunk 1 ----
    if (wid < 8) {
        #pragma unroll
        for (int j = 0; j < 8; ++j) xv[j] = *(const float4*)(xg + j * 4);
        #pragma unroll
        for (int j = 0; j < 4; ++j) wv[j] = *(const float4*)(wg + j * 4);
        char* buf = smem;
        #pragma unroll
        for (int jj = 0; jj < 4; ++jj) {
            float4 a = xv[2 * jj], b = xv[2 * jj + 1];
            uint4 hv, lv;
            split2(a.x, a.y, hv.x, lv.x); split2(a.z, a.w, hv.y, lv.y);
            split2(b.x, b.y, hv.z, lv.z); split2(b.z, b.w, hv.w, lv.w);
            const int off = (xr * TPAD + xc + 8 * jj) * 2;
            *(uint4*)(buf + XH_OFF + off) = hv;
            *(uint4*)(buf + XL_OFF + off) = lv;
        }
        #pragma unroll
        for (int jj = 0; jj < 2; ++jj) {
            float4 a = wv[2 * jj], b = wv[2 * jj + 1];
            uint4 hv, lv;
            split2(a.x * 64.f, a.y * 64.f, hv.x, lv.x); split2(a.z * 64.f, a.w * 64.f, hv.y, lv.y);
            split2(b.x * 64.f, b.y * 64.f, hv.z, lv.z); split2(b.z * 64.f, b.w * 64.f, hv.w, lv.w);
            const int off = (wr * TPAD + wc + 8 * jj) * 2;
            *(uint4*)(buf + WH_OFF + off) = hv;
            *(uint4*)(buf + WL_OFF + off) = lv;
        }
        // prefetch chunk 1
        #pragma unroll
        for (int j = 0; j < 8; ++j) xv[j] = *(const float4*)(xg + BK + j * 4);
        #pragma unroll
        for (int j = 0; j < 4; ++j) wv[j] = *(const float4*)(wg + BK + j * 4);
    }
    __syncthreads();

    // ---- main loop ----
    for (int c = 0; c < NCHUNK; ++c) {
        if (wid >= 8) {
            // CONSUMERS: MMA chunk c from buffer c&1
            const uint32_t base = sb + (uint32_t)((c & 1) * BUF_BYTES);
            #pragma unroll
            for (int ks = 0; ks < 4; ++ks) {
                unsigned ah[2][4], al[2][4];
                #pragma unroll
                for (int mt = 0; mt < 2; ++mt) {
                    ldsm4(ah[mt], base + XH_OFF + aOff[mt] + ks * 32);
                    ldsm4(al[mt], base + XL_OFF + aOff[mt] + ks * 32);
                }
                #pragma unroll
                for (int nt = 0; nt < 2; ++nt) {
                    const uint32_t boff = (uint32_t)(((n0 + nt * 16 + bRow) * TPAD + bK) * 2 + ks * 32);
                    unsigned bh[4], bl[4];
                    ldsm4(bh, base + WH_OFF + boff);
                    ldsm4(bl, base + WL_OFF + boff);
                    #pragma unroll
                    for (int mt = 0; mt < 2; ++mt) {
                        mma16816(acc[mt][2 * nt],     ah[mt], bh[0], bh[1]);
                        mma16816(acc[mt][2 * nt],     al[mt], bh[0], bh[1]);
                        mma16816(acc[mt][2 * nt],     ah[mt], bl[0], bl[1]);
                        mma16816(acc[mt][2 * nt + 1], ah[mt], bh[2], bh[3]);
                        mma16816(acc[mt][2 * nt + 1], al[mt], bh[2], bh[3]);
                        mma16816(acc[mt][2 * nt + 1], ah[mt], bl[2], bl[3]);
                    }
                }
            }
        } else {
            // PRODUCERS: convert chunk c+1 into buffer (c+1)&1, prefetch chunk c+2
            if (c + 1 < NCHUNK) {
                char* buf = smem + ((c + 1) & 1) * BUF_BYTES;
                #pragma unroll
                for (int jj = 0; jj < 4; ++jj) {
                    float4 a = xv[2 * jj], b = xv[2 * jj + 1];
                    uint4 hv, lv;
                    split2(a.x, a.y, hv.x, lv.x); split2(a.z, a.w, hv.y, lv.y);
                    split2(b.x, b.y, hv.z, lv.z); split2(b.z, b.w, hv.w, lv.w);
                    const int off = (xr * TPAD + xc + 8 * jj) * 2;
                    *(uint4*)(buf + XH_OFF + off) = hv;
                    *(uint4*)(buf + XL_OFF + off) = lv;
                }
                #pragma unroll
                for (int jj = 0; jj < 2; ++jj) {
                    float4 a = wv[2 * jj], b = wv[2 * jj + 1];
                    uint4 hv, lv;
                    split2(a.x * 64.f, a.y * 64.f, hv.x, lv.x); split2(a.z * 64.f, a.w * 64.f, hv.y, lv.y);
                    split2(b.x * 64.f, b.y * 64.f, hv.z, lv.z); split2(b.z * 64.f, b.w * 64.f, hv.w, lv.w);
                    const int off = (wr * TPAD + wc + 8 * jj) * 2;
                    *(uint4*)(buf + WH_OFF + off) = hv;
                    *(uint4*)(buf + WL_OFF + off) = lv;
                }
            }
            if (c + 2 < NCHUNK) {
                const int kt = (c + 2) * BK;
                #pragma unroll
                for (int j = 0; j < 8; ++j) xv[j] = *(const float4*)(xg + kt + j * 4);
                #pragma unroll
                for (int j = 0; j < 4; ++j) wv[j] = *(const float4*)(wg + kt + j * 4);
            }
        }
        __syncthreads();
    }

    // ---- consumers scatter logits (×1/64) to padded smem ----
    float* cs = (float*)smem;                 // [BM][65] = 33.3KB, aliases tiles
    if (wid >= 8) {
        const float inv64 = 0.015625f;
        const int qr = lane >> 2;
        const int qc = (lane & 3) * 2;
        #pragma unroll
        for (int mt = 0; mt < 2; ++mt) {
            #pragma unroll
            for (int j = 0; j < 4; ++j) {
                const int row = m0 + mt * 16 + qr;
                const int col = n0 + j * 8 + qc;
                cs[row * 65 + col]           = acc[mt][j][0] * inv64;
                cs[row * 65 + col + 1]       = acc[mt][j][1] * inv64;
                cs[(row + 8) * 65 + col]     = acc[mt][j][2] * inv64;
                cs[(row + 8) * 65 + col + 1] = acc[mt][j][3] * inv64;
            }
        }
    }
    __syncthreads();

    // ---- per-token top-2 / softmax / z partial (threads 0..127) ----
    if (tid < BM) {
        const float* row = &cs[tid * 65];
        float m1 = -3.4e38f, m2 = -3.4e38f;
        int i1 = 0, i2 = 0;
        #pragma unroll
        for (int e = 0; e < NEXP; ++e) {
            const float v = row[e];
            if (v > m1)      { m2 = m1; i2 = i1; m1 = v; i1 = e; }
            else if (v > m2) { m2 = v; i2 = e; }
        }
        float ssum = 0.f, sq = 0.f;
        #pragma unroll
        for (int e = 0; e < NEXP; ++e) {
            const float v = row[e];
            ssum += expf(v - m1);
            sq = fmaf(v, v, sq);
        }
        const int gi = tok0 + tid;
        const float inv = 1.0f / ssum;
        out[2 * gi + 0] = (float)i1;
        out[2 * gi + 1] = (float)i2;
        out[2 * T + 2 * gi + 0] = inv;
        out[2 * T + 2 * gi + 1] = expf(m2 - m1) * inv;
        zred[tid] = sq;
    }
    __syncthreads();

    // ---- deterministic z_loss ----
    if (tid == 0) {
        float s = 0.f;
        #pragma unroll
        for (int i = 0; i < BM; ++i) s += zred[i];
        g_z[blockIdx.x] = s;
        __threadfence();
        const unsigned t = atomicAdd(&g_cnt, 1);
        if (t == gridDim.x - 1) {
            float z = 0.f;
            for (unsigned i = 0; i < gridDim.x; ++i) z += g_z[i];
            out[4 * T + 0] = 0.0f;
            out[4 * T + 1] = z / ((float)T * (float)NEXP);
            g_cnt = 0;
        }
    }
}

extern "C" void kernel_launch(void* const* d_in, const int* in_sizes, int n_in,
                              void* d_out, int out_size) {
    const float* X = (const float*)d_in[0];
    const float* W = (const float*)d_in[1];
    float* out = (float*)d_out;
    const int T = in_sizes[0] / HDIM;     // 16384
    cudaFuncSetAttribute(router_ws, cudaFuncAttributeMaxDynamicSharedMemorySize, SMEM_TOTAL);
    router_ws<<<T / BM, NTHR, SMEM_TOTAL>>>(X, W, out, T);
}

// round 7
// speedup vs baseline: 1.4091x; 1.4091x over previous
#include <cuda_runtime.h>
#include <cuda_fp16.h>
#include <cstdint>

#define HDIM 4096
#define NEXP 64
#define BM   64       // tokens per CTA (halved -> 2 CTAs/SM)
#define BK   64
#define TPAD 72       // padded halves per smem row (144B)
#define NTHR 256

// dynamic smem (bytes), double buffered
#define XH_OFF 0
#define XL_OFF (BM * TPAD * 2)                  // 9216
#define WH_OFF (2 * BM * TPAD * 2)              // 18432
#define WL_OFF (WH_OFF + NEXP * TPAD * 2)       // 27648
#define BUF_BYTES (WL_OFF + NEXP * TPAD * 2)    // 36864
#define SMEM_TOTAL (2 * BUF_BYTES)              // 73728

__device__ float    g_z[256];     // per-CTA z partials (grid = 256)
__device__ unsigned g_cnt = 0;

__device__ __forceinline__ void split2(float f0, float f1, unsigned& hi, unsigned& lo) {
    __half2 h = __floats2half2_rn(f0, f1);
    float2 hf = __half22float2(h);
    __half2 l = __floats2half2_rn(f0 - hf.x, f1 - hf.y);
    hi = *reinterpret_cast<unsigned*>(&h);
    lo = *reinterpret_cast<unsigned*>(&l);
}
__device__ __forceinline__ void ldsm4(unsigned* d, uint32_t addr) {
    asm volatile("ldmatrix.sync.aligned.m8n8.x4.shared.b16 {%0,%1,%2,%3}, [%4];"
                 : "=r"(d[0]), "=r"(d[1]), "=r"(d[2]), "=r"(d[3]) : "r"(addr));
}
__device__ __forceinline__ void mma16816(float* c, const unsigned* a, unsigned b0, unsigned b1) {
    asm volatile("mma.sync.aligned.m16n8k16.row.col.f32.f16.f16.f32 "
                 "{%0,%1,%2,%3}, {%4,%5,%6,%7}, {%8,%9}, {%0,%1,%2,%3};"
                 : "+f"(c[0]), "+f"(c[1]), "+f"(c[2]), "+f"(c[3])
                 : "r"(a[0]), "r"(a[1]), "r"(a[2]), "r"(a[3]), "r"(b0), "r"(b1));
}

__global__ __launch_bounds__(NTHR, 2) void router_mma(
    const float* __restrict__ X, const float* __restrict__ W,
    float* __restrict__ out, int T)
{
    extern __shared__ char smem[];
    __shared__ float zred[BM];
    const uint32_t sb = (uint32_t)__cvta_generic_to_shared(smem);

    const int tid  = threadIdx.x;
    const int lane = tid & 31;
    const int warp = tid >> 5;          // 0..7
    const int tok0 = blockIdx.x * BM;

    // ---- global loaders: 4 thr/row, 16 floats each, for both X and W ----
    const int xr = tid >> 2, xc = (tid & 3) * 16;
    const float* xg = X + (size_t)(tok0 + xr) * HDIM + xc;
    const float* wg = W + (size_t)xr * HDIM + xc;

    // ---- warp tiling: 4 M-groups x 2 N-halves (m16n32, same as R4) ----
    const int m0 = (warp & 3) * 16;
    const int n0 = (warp >> 2) * 32;

    const int g = lane >> 3, r = lane & 7;
    const uint32_t aOff = (uint32_t)(((m0 + r + ((g & 1) << 3)) * TPAD + ((g >> 1) << 3)) * 2);
    const int bRow = r + ((g >> 1) << 3);
    const int bK   = (g & 1) << 3;

    float acc[4][4];
    #pragma unroll
    for (int i = 0; i < 4; ++i)
        #pragma unroll
        for (int j = 0; j < 4; ++j) acc[i][j] = 0.f;

    float4 xv[4], wv[4];

    // ---- preload + convert chunk 0 ----
    #pragma unroll
    for (int j = 0; j < 4; ++j) xv[j] = *(const float4*)(xg + j * 4);
    #pragma unroll
    for (int j = 0; j < 4; ++j) wv[j] = *(const float4*)(wg + j * 4);

    int p = 0;
    {
        char* buf = smem;
        #pragma unroll
        for (int jj = 0; jj < 2; ++jj) {
            float4 a = xv[2 * jj], b = xv[2 * jj + 1];
            uint4 hv, lv;
            split2(a.x, a.y, hv.x, lv.x); split2(a.z, a.w, hv.y, lv.y);
            split2(b.x, b.y, hv.z, lv.z); split2(b.z, b.w, hv.w, lv.w);
            const int off = (xr * TPAD + xc + 8 * jj) * 2;
            *(uint4*)(buf + XH_OFF + off) = hv;
            *(uint4*)(buf + XL_OFF + off) = lv;
        }
        #pragma unroll
        for (int jj = 0; jj < 2; ++jj) {
            float4 a = wv[2 * jj], b = wv[2 * jj + 1];
            uint4 hv, lv;
            split2(a.x * 64.f, a.y * 64.f, hv.x, lv.x); split2(a.z * 64.f, a.w * 64.f, hv.y, lv.y);
            split2(b.x * 64.f, b.y * 64.f, hv.z, lv.z); split2(b.z * 64.f, b.w * 64.f, hv.w, lv.w);
            const int off = (xr * TPAD + xc + 8 * jj) * 2;
            *(uint4*)(buf + WH_OFF + off) = hv;
            *(uint4*)(buf + WL_OFF + off) = lv;
        }
    }
    __syncthreads();

    // ---- main loop: prefetch k+1, MMA k, convert->other buffer ----
    for (int kt = BK; kt <= HDIM; kt += BK) {
        if (kt < HDIM) {
            #pragma unroll
            for (int j = 0; j < 4; ++j) xv[j] = *(const float4*)(xg + kt + j * 4);
            #pragma unroll
            for (int j = 0; j < 4; ++j) wv[j] = *(const float4*)(wg + kt + j * 4);
        }

        // MMA over buffer p
        {
            const uint32_t base = sb + (uint32_t)(p * BUF_BYTES);
            #pragma unroll
            for (int ks = 0; ks < 4; ++ks) {
                unsigned ah[4], al[4];
                ldsm4(ah, base + XH_OFF + aOff + ks * 32);
                ldsm4(al, base + XL_OFF + aOff + ks * 32);
                #pragma unroll
                for (int nt = 0; nt < 2; ++nt) {
                    const uint32_t boff = (uint32_t)(((n0 + nt * 16 + bRow) * TPAD + bK) * 2 + ks * 32);
                    unsigned bh[4], bl[4];
                    ldsm4(bh, base + WH_OFF + boff);
                    ldsm4(bl, base + WL_OFF + boff);
                    mma16816(acc[2 * nt],     ah, bh[0], bh[1]);
                    mma16816(acc[2 * nt],     al, bh[0], bh[1]);
                    mma16816(acc[2 * nt],     ah, bl[0], bl[1]);
                    mma16816(acc[2 * nt + 1], ah, bh[2], bh[3]);
                    mma16816(acc[2 * nt + 1], al, bh[2], bh[3]);
                    mma16816(acc[2 * nt + 1], ah, bl[2], bl[3]);
                }
            }
        }

        if (kt < HDIM) {
            char* buf = smem + (p ^ 1) * BUF_BYTES;
            #pragma unroll
            for (int jj = 0; jj < 2; ++jj) {
                float4 a = xv[2 * jj], b = xv[2 * jj + 1];
                uint4 hv, lv;
                split2(a.x, a.y, hv.x, lv.x); split2(a.z, a.w, hv.y, lv.y);
                split2(b.x, b.y, hv.z, lv.z); split2(b.z, b.w, hv.w, lv.w);
                const int off = (xr * TPAD + xc + 8 * jj) * 2;
                *(uint4*)(buf + XH_OFF + off) = hv;
                *(uint4*)(buf + XL_OFF + off) = lv;
            }
            #pragma unroll
            for (int jj = 0; jj < 2; ++jj) {
                float4 a = wv[2 * jj], b = wv[2 * jj + 1];
                uint4 hv, lv;
                split2(a.x * 64.f, a.y * 64.f, hv.x, lv.x); split2(a.z * 64.f, a.w * 64.f, hv.y, lv.y);
                split2(b.x * 64.f, b.y * 64.f, hv.z, lv.z); split2(b.z * 64.f, b.w * 64.f, hv.w, lv.w);
                const int off = (xr * TPAD + xc + 8 * jj) * 2;
                *(uint4*)(buf + WH_OFF + off) = hv;
                *(uint4*)(buf + WL_OFF + off) = lv;
            }
            __syncthreads();
            p ^= 1;
        }
    }

    __syncthreads();   // all MMA smem reads done before logits alias buffers

    // ---- scatter logits (×1/64) to padded smem ----
    float* cs = (float*)smem;                 // [BM][65] = 16.6KB
    const float inv64 = 0.015625f;
    const int qr = lane >> 2;
    const int qc = (lane & 3) * 2;
    #pragma unroll
    for (int j = 0; j < 4; ++j) {
        const int col = n0 + j * 8 + qc;
        cs[(m0 + qr)     * 65 + col]     = acc[j][0] * inv64;
        cs[(m0 + qr)     * 65 + col + 1] = acc[j][1] * inv64;
        cs[(m0 + qr + 8) * 65 + col]     = acc[j][2] * inv64;
        cs[(m0 + qr + 8) * 65 + col + 1] = acc[j][3] * inv64;
    }
    __syncthreads();

    // ---- per-token top-2 / softmax / z partial (threads 0..63) ----
    if (tid < BM) {
        const float* row = &cs[tid * 65];
        float m1 = -3.4e38f, m2 = -3.4e38f;
        int i1 = 0, i2 = 0;
        #pragma unroll
        for (int e = 0; e < NEXP; ++e) {
            const float v = row[e];
            if (v > m1)      { m2 = m1; i2 = i1; m1 = v; i1 = e; }
            else if (v > m2) { m2 = v; i2 = e; }
        }
        float ssum = 0.f, sq = 0.f;
        #pragma unroll
        for (int e = 0; e < NEXP; ++e) {
            const float v = row[e];
            ssum += expf(v - m1);
            sq = fmaf(v, v, sq);
        }
        const int gi = tok0 + tid;
        const float inv = 1.0f / ssum;
        out[2 * gi + 0] = (float)i1;
        out[2 * gi + 1] = (float)i2;
        out[2 * T + 2 * gi + 0] = inv;
        out[2 * T + 2 * gi + 1] = expf(m2 - m1) * inv;
        zred[tid] = sq;
    }
    __syncthreads();

    // ---- deterministic z_loss ----
    if (tid == 0) {
        float s = 0.f;
        #pragma unroll
        for (int i = 0; i < BM; ++i) s += zred[i];
        g_z[blockIdx.x] = s;
        __threadfence();
        const unsigned t = atomicAdd(&g_cnt, 1);
        if (t == gridDim.x - 1) {
            float z = 0.f;
            for (unsigned i = 0; i < gridDim.x; ++i) z += g_z[i];
            out[4 * T + 0] = 0.0f;
            out[4 * T + 1] = z / ((float)T * (float)NEXP);
            g_cnt = 0;
        }
    }
}

extern "C" void kernel_launch(void* const* d_in, const int* in_sizes, int n_in,
                              void* d_out, int out_size) {
    const float* X = (const float*)d_in[0];
    const float* W = (const float*)d_in[1];
    float* out = (float*)d_out;
    const int T = in_sizes[0] / HDIM;     // 16384
    cudaFuncSetAttribute(router_mma, cudaFuncAttributeMaxDynamicSharedMemorySize, SMEM_TOTAL);
    router_mma<<<T / BM, NTHR, SMEM_TOTAL>>>(X, W, out, T);
}

// round 8
// speedup vs baseline: 1.8667x; 1.3247x over previous
#include <cuda_runtime.h>
#include <cuda_fp16.h>
#include <cstdint>

#define HDIM 4096
#define NEXP 64
#define BM   128
#define BK   64
#define TPAD 72      // padded halves per smem row (144B)
#define NTHR 512

// dynamic smem (bytes), double buffered
#define XH_OFF 0
#define XL_OFF (BM * TPAD * 2)                  // 18432
#define WH_OFF (2 * BM * TPAD * 2)              // 36864
#define WL_OFF (WH_OFF + NEXP * TPAD * 2)       // 46080
#define BUF_BYTES (WL_OFF + NEXP * TPAD * 2)    // 55296
#define SMEM_TOTAL (2 * BUF_BYTES)              // 110592

__device__ float    g_z[128];
__device__ unsigned g_cnt = 0;

__device__ __forceinline__ void split2(float f0, float f1, unsigned& hi, unsigned& lo) {
    __half2 h = __floats2half2_rn(f0, f1);
    float2 hf = __half22float2(h);
    __half2 l = __floats2half2_rn(f0 - hf.x, f1 - hf.y);
    hi = *reinterpret_cast<unsigned*>(&h);
    lo = *reinterpret_cast<unsigned*>(&l);
}
__device__ __forceinline__ void ldsm4(unsigned* d, uint32_t addr) {
    asm volatile("ldmatrix.sync.aligned.m8n8.x4.shared.b16 {%0,%1,%2,%3}, [%4];"
                 : "=r"(d[0]), "=r"(d[1]), "=r"(d[2]), "=r"(d[3]) : "r"(addr));
}
__device__ __forceinline__ void mma16816(float* c, const unsigned* a, unsigned b0, unsigned b1) {
    asm volatile("mma.sync.aligned.m16n8k16.row.col.f32.f16.f16.f32 "
                 "{%0,%1,%2,%3}, {%4,%5,%6,%7}, {%8,%9}, {%0,%1,%2,%3};"
                 : "+f"(c[0]), "+f"(c[1]), "+f"(c[2]), "+f"(c[3])
                 : "r"(a[0]), "r"(a[1]), "r"(a[2]), "r"(a[3]), "r"(b0), "r"(b1));
}

__global__ __launch_bounds__(NTHR, 1) void router_mma(
    const float* __restrict__ X, const float* __restrict__ W,
    float* __restrict__ out, int T)
{
    extern __shared__ char smem[];
    __shared__ float zred[BM];
    const uint32_t sb = (uint32_t)__cvta_generic_to_shared(smem);

    const int tid  = threadIdx.x;
    const int lane = tid & 31;
    const int warp = tid >> 5;          // 0..15
    const int tok0 = blockIdx.x * BM;

    // ---- global loaders (identical to R4) ----
    const int xr = tid >> 2, xc = (tid & 3) * 16;   // X: 4 thr/row, 16 floats
    const int wr = tid >> 3, wc = (tid & 7) * 8;    // W: 8 thr/row,  8 floats
    const float* xg = X + (size_t)(tok0 + xr) * HDIM + xc;
    const float* wg = W + (size_t)wr * HDIM + wc;

    // ---- warp tiling: 8 m32n32 tiles, each shared by warp pair (w, w+8) ----
    // pair member 0 (warp<8) does ks 0-1 of each chunk; member 1 does ks 2-3.
    const int w2 = warp & 7;
    const int m0 = (w2 & 3) * 32;       // token rows m0..m0+31
    const int n0 = (w2 >> 2) * 32;      // expert cols n0..n0+31
    const int ksBase = (warp >> 3) * 2; // 0 or 2

    const int g = lane >> 3, r = lane & 7;
    uint32_t aOff[2];
    #pragma unroll
    for (int mt = 0; mt < 2; ++mt)
        aOff[mt] = (uint32_t)(((m0 + mt * 16 + r + ((g & 1) << 3)) * TPAD + ((g >> 1) << 3)) * 2);
    const int bRow = r + ((g >> 1) << 3);
    const int bK   = (g & 1) << 3;

    float acc[2][4][4];                 // [m16 sub-tile][n8 group][frag]
    #pragma unroll
    for (int mt = 0; mt < 2; ++mt)
        #pragma unroll
        for (int j = 0; j < 4; ++j)
            #pragma unroll
            for (int q = 0; q < 4; ++q) acc[mt][j][q] = 0.f;

    float4 xv[4], wv[2];

    // ---- preload + convert chunk 0 ----
    #pragma unroll
    for (int j = 0; j < 4; ++j) xv[j] = *(const float4*)(xg + j * 4);
    #pragma unroll
    for (int j = 0; j < 2; ++j) wv[j] = *(const float4*)(wg + j * 4);

    int p = 0;
    {
        char* buf = smem;
        #pragma unroll
        for (int jj = 0; jj < 2; ++jj) {
            float4 a = xv[2 * jj], b = xv[2 * jj + 1];
            uint4 hv, lv;
            split2(a.x, a.y, hv.x, lv.x); split2(a.z, a.w, hv.y, lv.y);
            split2(b.x, b.y, hv.z, lv.z); split2(b.z, b.w, hv.w, lv.w);
            const int off = (xr * TPAD + xc + 8 * jj) * 2;
            *(uint4*)(buf + XH_OFF + off) = hv;
            *(uint4*)(buf + XL_OFF + off) = lv;
        }
        {
            float4 a = wv[0], b = wv[1];
            uint4 hv, lv;
            split2(a.x * 64.f, a.y * 64.f, hv.x, lv.x); split2(a.z * 64.f, a.w * 64.f, hv.y, lv.y);
            split2(b.x * 64.f, b.y * 64.f, hv.z, lv.z); split2(b.z * 64.f, b.w * 64.f, hv.w, lv.w);
            const int off = (wr * TPAD + wc) * 2;
            *(uint4*)(buf + WH_OFF + off) = hv;
            *(uint4*)(buf + WL_OFF + off) = lv;
        }
    }
    __syncthreads();

    // ---- main loop: prefetch k+1, MMA k (2 ks per warp), convert->other buffer ----
    for (int kt = BK; kt <= HDIM; kt += BK) {
        if (kt < HDIM) {
            #pragma unroll
            for (int j = 0; j < 4; ++j) xv[j] = *(const float4*)(xg + kt + j * 4);
            #pragma unroll
            for (int j = 0; j < 2; ++j) wv[j] = *(const float4*)(wg + kt + j * 4);
        }

        {
            const uint32_t base = sb + (uint32_t)(p * BUF_BYTES);
            #pragma unroll
            for (int ksi = 0; ksi < 2; ++ksi) {
                const int ks = ksBase + ksi;
                unsigned ah[2][4], al[2][4];
                #pragma unroll
                for (int mt = 0; mt < 2; ++mt) {
                    ldsm4(ah[mt], base + XH_OFF + aOff[mt] + ks * 32);
                    ldsm4(al[mt], base + XL_OFF + aOff[mt] + ks * 32);
                }
                #pragma unroll
                for (int nt = 0; nt < 2; ++nt) {
                    const uint32_t boff = (uint32_t)(((n0 + nt * 16 + bRow) * TPAD + bK) * 2 + ks * 32);
                    unsigned bh[4], bl[4];
                    ldsm4(bh, base + WH_OFF + boff);
                    ldsm4(bl, base + WL_OFF + boff);
                    #pragma unroll
                    for (int mt = 0; mt < 2; ++mt) {
                        mma16816(acc[mt][2 * nt],     ah[mt], bh[0], bh[1]);
                        mma16816(acc[mt][2 * nt],     al[mt], bh[0], bh[1]);
                        mma16816(acc[mt][2 * nt],     ah[mt], bl[0], bl[1]);
                        mma16816(acc[mt][2 * nt + 1], ah[mt], bh[2], bh[3]);
                        mma16816(acc[mt][2 * nt + 1], al[mt], bh[2], bh[3]);
                        mma16816(acc[mt][2 * nt + 1], ah[mt], bl[2], bl[3]);
                    }
                }
            }
        }

        if (kt < HDIM) {
            char* buf = smem + (p ^ 1) * BUF_BYTES;
            #pragma unroll
            for (int jj = 0; jj < 2; ++jj) {
                float4 a = xv[2 * jj], b = xv[2 * jj + 1];
                uint4 hv, lv;
                split2(a.x, a.y, hv.x, lv.x); split2(a.z, a.w, hv.y, lv.y);
                split2(b.x, b.y, hv.z, lv.z); split2(b.z, b.w, hv.w, lv.w);
                const int off = (xr * TPAD + xc + 8 * jj) * 2;
                *(uint4*)(buf + XH_OFF + off) = hv;
                *(uint4*)(buf + XL_OFF + off) = lv;
            }
            {
                float4 a = wv[0], b = wv[1];
                uint4 hv, lv;
                split2(a.x * 64.f, a.y * 64.f, hv.x, lv.x); split2(a.z * 64.f, a.w * 64.f, hv.y, lv.y);
                split2(b.x * 64.f, b.y * 64.f, hv.z, lv.z); split2(b.z * 64.f, b.w * 64.f, hv.w, lv.w);
                const int off = (wr * TPAD + wc) * 2;
                *(uint4*)(buf + WH_OFF + off) = hv;
                *(uint4*)(buf + WL_OFF + off) = lv;
            }
            __syncthreads();
            p ^= 1;
        }
    }

    __syncthreads();   // all MMA smem reads done before logits alias buffers

    // ---- two-phase merge of warp-pair partials into padded smem ----
    float* cs = (float*)smem;                 // [BM][65]
    const float inv64 = 0.015625f;
    const int qr = lane >> 2;
    const int qc = (lane & 3) * 2;
    if (warp >= 8) {                          // phase 1: store ks{2,3} partials
        #pragma unroll
        for (int mt = 0; mt < 2; ++mt)
            #pragma unroll
            for (int j = 0; j < 4; ++j) {
                const int row = m0 + mt * 16 + qr;
                const int col = n0 + j * 8 + qc;
                cs[row * 65 + col]           = acc[mt][j][0] * inv64;
                cs[row * 65 + col + 1]       = acc[mt][j][1] * inv64;
                cs[(row + 8) * 65 + col]     = acc[mt][j][2] * inv64;
                cs[(row + 8) * 65 + col + 1] = acc[mt][j][3] * inv64;
            }
    }
    __syncthreads();
    if (warp < 8) {                           // phase 2: add ks{0,1} partials
        #pragma unroll
        for (int mt = 0; mt < 2; ++mt)
            #pragma unroll
            for (int j = 0; j < 4; ++j) {
                const int row = m0 + mt * 16 + qr;
                const int col = n0 + j * 8 + qc;
                cs[row * 65 + col]           += acc[mt][j][0] * inv64;
                cs[row * 65 + col + 1]       += acc[mt][j][1] * inv64;
                cs[(row + 8) * 65 + col]     += acc[mt][j][2] * inv64;
                cs[(row + 8) * 65 + col + 1] += acc[mt][j][3] * inv64;
            }
    }
    __syncthreads();

    // ---- per-token top-2 / softmax / z partial (threads 0..127) ----
    if (tid < BM) {
        const float* row = &cs[tid * 65];
        float m1 = -3.4e38f, m2 = -3.4e38f;
        int i1 = 0, i2 = 0;
        #pragma unroll
        for (int e = 0; e < NEXP; ++e) {
            const float v = row[e];
            if (v > m1)      { m2 = m1; i2 = i1; m1 = v; i1 = e; }
            else if (v > m2) { m2 = v; i2 = e; }
        }
        float ssum = 0.f, sq = 0.f;
        #pragma unroll
        for (int e = 0; e < NEXP; ++e) {
            const float v = row[e];
            ssum += expf(v - m1);
            sq = fmaf(v, v, sq);
        }
        const int gi = tok0 + tid;
        const float inv = 1.0f / ssum;
        out[2 * gi + 0] = (float)i1;
        out[2 * gi + 1] = (float)i2;
        out[2 * T + 2 * gi + 0] = inv;
        out[2 * T + 2 * gi + 1] = expf(m2 - m1) * inv;
        zred[tid] = sq;
    }
    __syncthreads();

    // ---- deterministic z_loss ----
    if (tid == 0) {
        float s = 0.f;
        #pragma unroll
        for (int i = 0; i < BM; ++i) s += zred[i];
        g_z[blockIdx.x] = s;
        __threadfence();
        const unsigned t = atomicAdd(&g_cnt, 1);
        if (t == gridDim.x - 1) {
            float z = 0.f;
            for (unsigned i = 0; i < gridDim.x; ++i) z += g_z[i];
            out[4 * T + 0] = 0.0f;
            out[4 * T + 1] = z / ((float)T * (float)NEXP);
            g_cnt = 0;
        }
    }
}

extern "C" void kernel_launch(void* const* d_in, const int* in_sizes, int n_in,
                              void* d_out, int out_size) {
    const float* X = (const float*)d_in[0];
    const float* W = (const float*)d_in[1];
    float* out = (float*)d_out;
    const int T = in_sizes[0] / HDIM;     // 16384
    cudaFuncSetAttribute(router_mma, cudaFuncAttributeMaxDynamicSharedMemorySize, SMEM_TOTAL);
    router_mma<<<T / BM, NTHR, SMEM_TOTAL>>>(X, W, out, T);
}